// round 15
// baseline (speedup 1.0000x reference)
#include <cuda_runtime.h>
#include <cstdint>

#define MAXB 65536
#define BLK 256
#define MAXG (MAXB / BLK)    // 256 tiles of 256 batches

// Scratch (allocation-free __device__ globals).
// g_meta[b]: os_loc(18) | ns_loc(18)<<18 | f(10)<<36  (offsets local to tile)
// g_agg[t]:  packed tile totals: span_sum(lo32) | filter_sum(hi32)
__device__ unsigned long long g_meta[MAXB];
__device__ unsigned long long g_agg[MAXG];

__device__ __forceinline__ unsigned long long pack2(int span, int filt) {
    return (unsigned long long)(unsigned int)span |
           ((unsigned long long)(unsigned int)filt << 32);
}

// ---------------------------------------------------------------------------
// Scan kernel: grid = 256 blocks, 1 batch/thread, tile = 256 batches.
// Per-tile local exclusive scan + tile aggregate. No cross-block traffic.
// ---------------------------------------------------------------------------
__global__ void __launch_bounds__(BLK) scan_kernel(
        const int* __restrict__ al, const int* __restrict__ alf, int B) {
    __shared__ unsigned long long s_wexcl[BLK / 32];
    __shared__ unsigned long long s_wtot[BLK / 32];

    const int t = threadIdx.x, lane = t & 31, wid = t >> 5;
    const int i = blockIdx.x * BLK + t;

    unsigned long long p = (i < B) ? pack2(al[i] + 1, alf[i]) : 0ull;

    // Warp-inclusive scan.
    unsigned long long incl = p;
    #pragma unroll
    for (int o = 1; o < 32; o <<= 1) {
        unsigned long long n = __shfl_up_sync(0xffffffffu, incl, o);
        if (lane >= o) incl += n;
    }
    unsigned long long texcl = incl - p;
    if (lane == 31) s_wtot[wid] = incl;
    __syncthreads();

    // Warp 0: scan the 8 warp totals; lane 7 stores the tile aggregate.
    if (wid == 0) {
        unsigned long long v = (lane < BLK / 32) ? s_wtot[lane] : 0ull;
        unsigned long long inc = v;
        #pragma unroll
        for (int o = 1; o < BLK / 32; o <<= 1) {
            unsigned long long n = __shfl_up_sync(0xffffffffu, inc, o);
            if (lane >= o) inc += n;
        }
        if (lane < BLK / 32) s_wexcl[lane] = inc - v;
        if (lane == BLK / 32 - 1) g_agg[blockIdx.x] = inc;
    }
    __syncthreads();

    if (i < B) {
        unsigned long long run = s_wexcl[wid] + texcl;    // local exclusive
        unsigned long long os = run & 0xffffffffull;      // < 131328 < 2^18
        unsigned long long ns = run >> 32;                // <= os
        unsigned long long fv = p >> 32;                  // <= 512 < 2^10
        g_meta[i] = os | (ns << 18) | (fv << 36);
    }
}

// ---------------------------------------------------------------------------
// Copy body: NS lane-contiguous 32-element chunks; every LDG/STG is one
// 128B wavefront; all loads issued before any store (MLP = NS). Streaming
// hints (.cs) — measured faster than default caching (R10 vs R12).
// ---------------------------------------------------------------------------
template<int NS>
__device__ __forceinline__ void chunk_body(const float* __restrict__ s,
                                           float* __restrict__ d,
                                           int len, int lane) {
    float x[NS];
    #pragma unroll
    for (int k = 0; k < NS; k++) {
        int i = lane + k * 32;
        x[k] = (i < len) ? __ldcs(s + i) : 0.0f;
    }
    #pragma unroll
    for (int k = 0; k < NS; k++) {
        int i = lane + k * 32;
        if (i < len) __stcs(d + i, x[k]);
    }
}

// ---------------------------------------------------------------------------
// Copy: TWO warps per batch (each takes half) -> max per-warp work is 8
// chunks, halving the straggler tail. Tile base reconstructed per warp from
// the 256 tile aggregates (8 loads/lane + butterfly).
// ---------------------------------------------------------------------------
__global__ void __launch_bounds__(256) copy_kernel(
        const float* __restrict__ src, float* __restrict__ out, int B) {
    int gw   = (blockIdx.x * blockDim.x + threadIdx.x) >> 5;
    int lane = threadIdx.x & 31;
    int b    = gw >> 1;          // batch
    int h    = gw & 1;           // half index (0 = first half, 1 = second)
    if (b >= B) return;

    unsigned long long m = g_meta[b];      // broadcast 8B load
    int f = (int)(m >> 36) & 0x3ff;

    // This warp's half: [beg, beg+len) of the batch.
    int half = (f + 1) >> 1;               // ceil(f/2)
    int beg  = h ? half : 0;
    int len  = h ? (f - half) : half;
    if (len <= 0) return;                  // covers f==0 and odd tails

    int tile = b >> 8;                     // 256 batches per tile

    // Tile base: masked sum of preceding tile aggregates (256 entries).
    unsigned long long v = 0;
    #pragma unroll
    for (int k = 0; k < MAXG / 32; k++) {
        int j = lane + k * 32;
        unsigned long long a = g_agg[j];   // L1/L2-hot 2KB table
        if (j < tile) v += a;
    }
    #pragma unroll
    for (int o = 16; o > 0; o >>= 1)
        v += __shfl_xor_sync(0xffffffffu, v, o);

    const float* s = src + (int)(v & 0xffffffffull) + (int)(m & 0x3ffffull) + beg;
    float*       d = out + (int)(v >> 32)           + (int)((m >> 18) & 0x3ffffull) + beg;

    // Ladder on chunk count (len <= 256 -> 1..8 chunks).
    switch ((len + 31) >> 5) {
        case 1: chunk_body<1>(s, d, len, lane); break;
        case 2: chunk_body<2>(s, d, len, lane); break;
        case 3: chunk_body<3>(s, d, len, lane); break;
        case 4: chunk_body<4>(s, d, len, lane); break;
        case 5: chunk_body<5>(s, d, len, lane); break;
        case 6: chunk_body<6>(s, d, len, lane); break;
        case 7: chunk_body<7>(s, d, len, lane); break;
        default: chunk_body<8>(s, d, len, lane); break;
    }
}

// ---------------------------------------------------------------------------
// Launch: 2 plain kernels (PDL reverted — measured regression in R12).
// ---------------------------------------------------------------------------
extern "C" void kernel_launch(void* const* d_in, const int* in_sizes, int n_in,
                              void* d_out, int out_size) {
    const float* tgt_cache_loc = (const float*)d_in[0];
    const int*   accept_length = (const int*)d_in[1];
    const int*   accept_filter = (const int*)d_in[2];
    (void)n_in; (void)out_size;

    int B = in_sizes[1];
    int G = (B + BLK - 1) / BLK;

    scan_kernel<<<G, BLK>>>(accept_length, accept_filter, B);

    int warps  = 2 * B;                    // two warps per batch
    int blocks = (warps * 32 + 255) / 256;
    copy_kernel<<<blocks, 256>>>(tgt_cache_loc, (float*)d_out, B);
}

// round 16
// speedup vs baseline: 1.2390x; 1.2390x over previous
#include <cuda_runtime.h>
#include <cstdint>

#define MAXB 65536
#define BLK 256
#define MAXG (MAXB / BLK)    // 256 tiles of 256 batches
#define BPB 8                // batches (warps) per copy block

// Scratch (allocation-free __device__ globals).
// g_meta[b]: os_loc(18) | ns_loc(18)<<18 | f(10)<<36  (offsets local to tile)
// g_agg[t]:  packed tile totals: span_sum(lo32) | filter_sum(hi32)
__device__ unsigned long long g_meta[MAXB];
__device__ unsigned long long g_agg[MAXG];

__device__ __forceinline__ unsigned long long pack2(int span, int filt) {
    return (unsigned long long)(unsigned int)span |
           ((unsigned long long)(unsigned int)filt << 32);
}

// ---------------------------------------------------------------------------
// Scan kernel: 256 blocks, 1 batch/thread, tile = 256 batches.
// Per-tile local exclusive scan + tile aggregate. Measured fast (~0.5-1us
// incl. gap in R14). No cross-block traffic.
// ---------------------------------------------------------------------------
__global__ void __launch_bounds__(BLK) scan_kernel(
        const int* __restrict__ al, const int* __restrict__ alf, int B) {
    __shared__ unsigned long long s_wexcl[BLK / 32];
    __shared__ unsigned long long s_wtot[BLK / 32];

    const int t = threadIdx.x, lane = t & 31, wid = t >> 5;
    const int i = blockIdx.x * BLK + t;

    unsigned long long p = (i < B) ? pack2(al[i] + 1, alf[i]) : 0ull;

    unsigned long long incl = p;
    #pragma unroll
    for (int o = 1; o < 32; o <<= 1) {
        unsigned long long n = __shfl_up_sync(0xffffffffu, incl, o);
        if (lane >= o) incl += n;
    }
    unsigned long long texcl = incl - p;
    if (lane == 31) s_wtot[wid] = incl;
    __syncthreads();

    if (wid == 0) {
        unsigned long long v = (lane < BLK / 32) ? s_wtot[lane] : 0ull;
        unsigned long long inc = v;
        #pragma unroll
        for (int o = 1; o < BLK / 32; o <<= 1) {
            unsigned long long n = __shfl_up_sync(0xffffffffu, inc, o);
            if (lane >= o) inc += n;
        }
        if (lane < BLK / 32) s_wexcl[lane] = inc - v;
        if (lane == BLK / 32 - 1) g_agg[blockIdx.x] = inc;
    }
    __syncthreads();

    if (i < B) {
        unsigned long long run = s_wexcl[wid] + texcl;    // local exclusive
        unsigned long long os = run & 0xffffffffull;      // < 131328 < 2^18
        unsigned long long ns = run >> 32;                // <= os
        unsigned long long fv = p >> 32;                  // <= 512 < 2^10
        g_meta[i] = os | (ns << 18) | (fv << 36);
    }
}

// ---------------------------------------------------------------------------
// Copy body: NS lane-contiguous 32-element chunks; every LDG/STG is one
// 128B wavefront; all loads issued before any store (MLP = NS). Streaming
// hints (.cs) — measured faster than default caching.
// ---------------------------------------------------------------------------
template<int NS>
__device__ __forceinline__ void chunk_body(const float* __restrict__ s,
                                           float* __restrict__ d,
                                           int len, int lane) {
    float x[NS];
    #pragma unroll
    for (int k = 0; k < NS; k++) {
        int i = lane + k * 32;
        x[k] = (i < len) ? __ldcs(s + i) : 0.0f;
    }
    #pragma unroll
    for (int k = 0; k < NS; k++) {
        int i = lane + k * 32;
        if (i < len) __stcs(d + i, x[k]);
    }
}

// ---------------------------------------------------------------------------
// Copy: one warp per batch, 8 batches per block. A block's batches span at
// most 2 tiles; warps 0/1 compute those tile bases once (amortized 8x),
// shared via smem. Then one u64 metadata broadcast + f-ladder copy.
// ---------------------------------------------------------------------------
__global__ void __launch_bounds__(256) copy_kernel(
        const float* __restrict__ src, float* __restrict__ out, int B) {
    __shared__ unsigned long long s_base[2];

    const int lane = threadIdx.x & 31, wid = threadIdx.x >> 5;
    const int b0 = blockIdx.x * BPB;
    const int t0 = b0 >> 8;                    // tile of first batch
    const int t1 = (b0 + BPB - 1) >> 8;        // tile of last batch (t0 or t0+1)

    // Warps 0/1: base for t0 / t1 (masked sum over the 2KB agg table).
    if (wid < 2) {
        int tt = (wid == 0) ? t0 : t1;
        unsigned long long v = 0;
        #pragma unroll
        for (int k = 0; k < MAXG / 32; k++) {
            int j = lane + k * 32;
            unsigned long long a = g_agg[j];
            if (j < tt) v += a;
        }
        #pragma unroll
        for (int o = 16; o > 0; o >>= 1)
            v += __shfl_xor_sync(0xffffffffu, v, o);
        if (lane == 0) s_base[wid] = v;
    }
    __syncthreads();

    const int b = b0 + wid;
    if (b >= B) return;

    unsigned long long m = g_meta[b];          // broadcast 8B load
    int f = (int)(m >> 36) & 0x3ff;
    if (f == 0) return;

    unsigned long long v = s_base[(b >> 8) != t0];
    const float* s = src + (int)(v & 0xffffffffull) + (int)(m & 0x3ffffull);
    float*       d = out + (int)(v >> 32)           + (int)((m >> 18) & 0x3ffffull);

    // Ladder on chunk count, even steps (f <= 512 -> up to 16 chunks).
    switch ((f + 63) >> 6) {                   // ceil(f/64) in 1..8
        case 1: chunk_body<2>(s, d, f, lane); break;
        case 2: chunk_body<4>(s, d, f, lane); break;
        case 3: chunk_body<6>(s, d, f, lane); break;
        case 4: chunk_body<8>(s, d, f, lane); break;
        case 5: chunk_body<10>(s, d, f, lane); break;
        case 6: chunk_body<12>(s, d, f, lane); break;
        case 7: chunk_body<14>(s, d, f, lane); break;
        default: chunk_body<16>(s, d, f, lane); break;
    }
}

// ---------------------------------------------------------------------------
// Launch: 2 plain kernels.
// ---------------------------------------------------------------------------
extern "C" void kernel_launch(void* const* d_in, const int* in_sizes, int n_in,
                              void* d_out, int out_size) {
    const float* tgt_cache_loc = (const float*)d_in[0];
    const int*   accept_length = (const int*)d_in[1];
    const int*   accept_filter = (const int*)d_in[2];
    (void)n_in; (void)out_size;

    int B = in_sizes[1];
    int G = (B + BLK - 1) / BLK;

    scan_kernel<<<G, BLK>>>(accept_length, accept_filter, B);

    int blocks = (B + BPB - 1) / BPB;          // 8 warps = 8 batches per block
    copy_kernel<<<blocks, 256>>>(tgt_cache_loc, (float*)d_out, B);
}